// round 12
// baseline (speedup 1.0000x reference)
#include <cuda_runtime.h>

#define NTHR 128
#define CPS  16                          // CTAs per SM
#define NBLK (CPS * 148)                 // 2368 blocks = one full wave, 64 warps/SM

__device__ float        g_partials[NBLK];
__device__ unsigned int g_count = 0;

// Raw MUFU.LG2 — inputs guaranteed in [1e-4, 1-1e-4] (always normal).
__device__ __forceinline__ float lg2_raw(float x) {
    float r;
    asm("lg2.approx.ftz.f32 %0, %1;" : "=f"(r) : "f"(x));
    return r;
}

// FMA-pipe log2 (degree-7 Horner, lg2 units): offloads 1 of 4 logs from the
// MUFU pipe. Coefficients are immediates (no register cost). Max abs err
// ~1.7e-4 lg2-units -> far inside the 1e-3 gate (measured rel_err 4.2e-6).
__device__ __forceinline__ float lg2_poly(float x) {
    int   xi = __float_as_int(x);
    int   k  = xi - 0x3f3504f3;          // center mantissa at sqrt(2)
    int   eb = k & 0xff800000;
    float m  = __int_as_float(xi - eb);  // [0.7071, 1.4142)
    float e  = (float)(eb >> 23);
    float f  = m - 1.0f;
    float r  =            0.20609929f;
    r = fmaf(r, f, -0.24044917f);
    r = fmaf(r, f,  0.28853901f);
    r = fmaf(r, f, -0.36067376f);
    r = fmaf(r, f,  0.48089835f);
    r = fmaf(r, f, -0.72134752f);
    r = fmaf(r, f,  1.44269504f);
    return fmaf(r, f, e);
}

// Binary KL in log2 units; 3 MUFU + 1 poly per element, two accumulators.
__device__ __forceinline__ void kl2_acc(float p, float q,
                                        float& accA, float& accB) {
    float omp = 1.0f - p;
    float omq = 1.0f - q;
    float d1  = lg2_raw(p)   - lg2_raw(q);
    float d2  = lg2_raw(omp) - lg2_poly(omq);
    accA = fmaf(p,   d1, accA);
    accB = fmaf(omp, d2, accB);
}

__global__ void __launch_bounds__(NTHR, CPS)   // 32-reg cap -> 64 warps/SM
kl_fused(const float* __restrict__ p, const float* __restrict__ q,
         int n, float* __restrict__ out) {
    const int nvec = n >> 2;
    const float4* __restrict__ p4 = reinterpret_cast<const float4*>(p);
    const float4* __restrict__ q4 = reinterpret_cast<const float4*>(q);

    float accA = 0.0f, accB = 0.0f;   // log2 units

    // Simple grid-stride, VPT=1: minimal live registers; latency hidden by
    // 16 warps/SMSP. Fine-grained 128-thread CTAs shrink epilogue tails.
    const int stride = NBLK * NTHR;
    for (int i = blockIdx.x * NTHR + threadIdx.x; i < nvec; i += stride) {
        float4 a = __ldcs(&p4[i]);
        float4 b = __ldcs(&q4[i]);
        kl2_acc(a.x, b.x, accA, accB);
        kl2_acc(a.y, b.y, accA, accB);
        kl2_acc(a.z, b.z, accA, accB);
        kl2_acc(a.w, b.w, accA, accB);
    }

    // Scalar tail (n % 4): last block only.
    if (blockIdx.x == gridDim.x - 1) {
        for (int i = (nvec << 2) + threadIdx.x; i < n; i += NTHR)
            kl2_acc(p[i], q[i], accA, accB);
    }

    float acc = (accA + accB) * 0.6931471805599453f;   // log2 -> ln, once

    // Block reduce (fixed tree -> deterministic): 4 warps.
    #pragma unroll
    for (int o = 16; o > 0; o >>= 1)
        acc += __shfl_down_sync(0xffffffffu, acc, o);
    __shared__ float s[NTHR / 32];
    if ((threadIdx.x & 31) == 0) s[threadIdx.x >> 5] = acc;
    __syncthreads();
    float bsum = 0.0f;
    if (threadIdx.x < 32) {
        bsum = (threadIdx.x < NTHR / 32) ? s[threadIdx.x] : 0.0f;
        #pragma unroll
        for (int o = (NTHR / 64); o > 0; o >>= 1)
            bsum += __shfl_down_sync(0xffffffffu, bsum, o);
    }

    __shared__ bool is_last;
    if (threadIdx.x == 0) {
        g_partials[blockIdx.x] = bsum;
        __threadfence();
        // atomicInc wraps to 0 at gridDim.x-1 -> self-resetting, graph-replay safe.
        unsigned int done = atomicInc(&g_count, gridDim.x - 1);
        is_last = (done == gridDim.x - 1);
    }
    __syncthreads();

    if (is_last) {
        // Deterministic fixed-order final reduce in fp64 (2368 partials).
        double dacc = 0.0;
        for (int i = threadIdx.x; i < gridDim.x; i += NTHR)
            dacc += (double)g_partials[i];
        #pragma unroll
        for (int o = 16; o > 0; o >>= 1)
            dacc += __shfl_down_sync(0xffffffffu, dacc, o);
        __shared__ double sd[NTHR / 32];
        if ((threadIdx.x & 31) == 0) sd[threadIdx.x >> 5] = dacc;
        __syncthreads();
        if (threadIdx.x == 0) {
            double t = 0.0;
            #pragma unroll
            for (int w = 0; w < NTHR / 32; w++) t += sd[w];
            out[0] = (float)t;
        }
    }
}

extern "C" void kernel_launch(void* const* d_in, const int* in_sizes, int n_in,
                              void* d_out, int out_size) {
    const float* p = (const float*)d_in[0];
    const float* q = (const float*)d_in[1];
    float* out = (float*)d_out;
    int n = in_sizes[0];

    kl_fused<<<NBLK, NTHR>>>(p, q, n, out);
}

// round 13
// speedup vs baseline: 1.0192x; 1.0192x over previous
#include <cuda_runtime.h>

#define NTHR 256
#define NBLK 1184                        // 8 blocks/SM x 148 SMs = one full wave

__device__ float        g_partials[NBLK];
__device__ unsigned int g_count = 0;

// Raw MUFU.LG2 — inputs guaranteed in [1e-4, 1-1e-4] (always normal).
__device__ __forceinline__ float lg2_raw(float x) {
    float r;
    asm("lg2.approx.ftz.f32 %0, %1;" : "=f"(r) : "f"(x));
    return r;
}

// FMA-pipe log2 (degree-7 Horner, lg2 units): offloads 1 of 4 logs from the
// MUFU pipe. Coefficients are immediates (no register cost). Max abs err
// ~1.7e-4 lg2-units -> far inside the 1e-3 gate (measured rel_err 4.2e-6).
__device__ __forceinline__ float lg2_poly(float x) {
    int   xi = __float_as_int(x);
    int   k  = xi - 0x3f3504f3;          // center mantissa at sqrt(2)
    int   eb = k & 0xff800000;
    float m  = __int_as_float(xi - eb);  // [0.7071, 1.4142)
    float e  = (float)(eb >> 23);
    float f  = m - 1.0f;
    float r  =            0.20609929f;
    r = fmaf(r, f, -0.24044917f);
    r = fmaf(r, f,  0.28853901f);
    r = fmaf(r, f, -0.36067376f);
    r = fmaf(r, f,  0.48089835f);
    r = fmaf(r, f, -0.72134752f);
    r = fmaf(r, f,  1.44269504f);
    return fmaf(r, f, e);
}

// Binary KL in log2 units; 3 MUFU + 1 poly per element, two accumulators.
__device__ __forceinline__ void kl2_acc(float p, float q,
                                        float& accA, float& accB) {
    float omp = 1.0f - p;
    float omq = 1.0f - q;
    float d1  = lg2_raw(p)   - lg2_raw(q);
    float d2  = lg2_raw(omp) - lg2_poly(omq);
    accA = fmaf(p,   d1, accA);
    accB = fmaf(omp, d2, accB);
}

__global__ void __launch_bounds__(NTHR, 8)   // cap 32 regs -> 64 warps/SM
kl_fused(const float* __restrict__ p, const float* __restrict__ q,
         int n, float* __restrict__ out) {
    const int nvec = n >> 2;
    const float4* __restrict__ p4 = reinterpret_cast<const float4*>(p);
    const float4* __restrict__ q4 = reinterpret_cast<const float4*>(q);

    float accA = 0.0f, accB = 0.0f;   // log2 units

    // Simple grid-stride, VPT=1: minimal live registers (fits 32-reg cap
    // without spill); latency hidden by 16 warps/SMSP.
    const int stride = NBLK * NTHR;
    for (int i = blockIdx.x * NTHR + threadIdx.x; i < nvec; i += stride) {
        float4 a = __ldcs(&p4[i]);
        float4 b = __ldcs(&q4[i]);
        kl2_acc(a.x, b.x, accA, accB);
        kl2_acc(a.y, b.y, accA, accB);
        kl2_acc(a.z, b.z, accA, accB);
        kl2_acc(a.w, b.w, accA, accB);
    }

    // Scalar tail (n % 4): last block only.
    if (blockIdx.x == gridDim.x - 1) {
        for (int i = (nvec << 2) + threadIdx.x; i < n; i += NTHR)
            kl2_acc(p[i], q[i], accA, accB);
    }

    float acc = (accA + accB) * 0.6931471805599453f;   // log2 -> ln, once

    // Block reduce (fixed tree -> deterministic)
    #pragma unroll
    for (int o = 16; o > 0; o >>= 1)
        acc += __shfl_down_sync(0xffffffffu, acc, o);
    __shared__ float s[NTHR / 32];
    if ((threadIdx.x & 31) == 0) s[threadIdx.x >> 5] = acc;
    __syncthreads();
    float bsum = 0.0f;
    if (threadIdx.x < 32) {
        bsum = (threadIdx.x < NTHR / 32) ? s[threadIdx.x] : 0.0f;
        #pragma unroll
        for (int o = (NTHR / 64); o > 0; o >>= 1)
            bsum += __shfl_down_sync(0xffffffffu, bsum, o);
    }

    __shared__ bool is_last;
    if (threadIdx.x == 0) {
        g_partials[blockIdx.x] = bsum;
        __threadfence();
        // atomicInc wraps to 0 at gridDim.x-1 -> self-resetting, graph-replay safe.
        unsigned int done = atomicInc(&g_count, gridDim.x - 1);
        is_last = (done == gridDim.x - 1);
    }
    __syncthreads();

    if (is_last) {
        // Deterministic fixed-order final reduce in fp64.
        double dacc = 0.0;
        for (int i = threadIdx.x; i < gridDim.x; i += NTHR)
            dacc += (double)g_partials[i];
        #pragma unroll
        for (int o = 16; o > 0; o >>= 1)
            dacc += __shfl_down_sync(0xffffffffu, dacc, o);
        __shared__ double sd[NTHR / 32];
        if ((threadIdx.x & 31) == 0) sd[threadIdx.x >> 5] = dacc;
        __syncthreads();
        if (threadIdx.x == 0) {
            double t = 0.0;
            #pragma unroll
            for (int w = 0; w < NTHR / 32; w++) t += sd[w];
            out[0] = (float)t;
        }
    }
}

extern "C" void kernel_launch(void* const* d_in, const int* in_sizes, int n_in,
                              void* d_out, int out_size) {
    const float* p = (const float*)d_in[0];
    const float* q = (const float*)d_in[1];
    float* out = (float*)d_out;
    int n = in_sizes[0];

    kl_fused<<<NBLK, NTHR>>>(p, q, n, out);
}